// round 2
// baseline (speedup 1.0000x reference)
#include <cuda_runtime.h>
#include <cstdint>

// Problem dims (fixed by the dataset)
//  x: (2,1024,32,512)  -> M = 65536 rows of 512
//  hidden = 512 (8 heads x 64), w_kv -> 1024 cols
#define M_TOTAL 65536
#define NPOS 32
#define NHEAD 8
#define DHEAD 64

// ---------------- scratch (device globals; no runtime allocation) ----------
__device__ float g_Q[(size_t)M_TOTAL * 512];
__device__ float g_K[(size_t)M_TOTAL * 512];
__device__ float g_V[(size_t)M_TOTAL * 512];
__device__ float g_AO[(size_t)M_TOTAL * 512];
__device__ float g_cos[NPOS * 32];
__device__ float g_sin[NPOS * 32];
__device__ int   g_mask[2];

// ---------------- helpers ---------------------------------------------------
__device__ __forceinline__ uint32_t f2tf32(float x) {
    uint32_t r;
    asm("cvt.rna.tf32.f32 %0, %1;" : "=r"(r) : "f"(x));
    return r;
}

// Normalize the focus mask regardless of serialized dtype (uint8 vs int32).
// If both 32-bit words are <= 1, the buffer is consistent with int32 {0,1}
// values (also covers uint8 [v,0] with zero padding, same answer). Otherwise
// interpret bytes. Reading 8 bytes is safe: device allocs are >=256B granular.
__global__ void mask_norm_kernel(const uint32_t* __restrict__ m) {
    uint32_t w0 = m[0], w1 = m[1];
    if (w0 <= 1u && w1 <= 1u) {
        g_mask[0] = (int)w0; g_mask[1] = (int)w1;
    } else {
        const unsigned char* p = (const unsigned char*)m;
        g_mask[0] = p[0] ? 1 : 0; g_mask[1] = p[1] ? 1 : 0;
    }
}

// RoPE cos/sin table: 32 positions x 32 freqs
__global__ void rope_table_kernel(const float* __restrict__ inv_freq) {
    int t = threadIdx.x;           // 1024 threads
    int pos = t >> 5;
    int i = t & 31;
    float ang = (float)pos * inv_freq[i];
    g_cos[t] = cosf(ang);
    g_sin[t] = sinf(ang);
}

// Epilogue store for the fused QKV GEMM.
// c in [0,1536): seg 0 = Q (scale+rope), 1 = K (rope), 2 = V (raw)
__device__ __forceinline__ void epi_store(int r, int c, float v0, float v1) {
    int seg = c >> 9;
    int off = c & 511;
    size_t p = (size_t)r * 512 + off;
    if (seg == 2) {
        *(float2*)(g_V + p) = make_float2(v0, v1);
    } else {
        int pos = r & 31;               // position within the 32-length axis
        int fi = (c & 63) >> 1;         // freq index within head dim
        float cs = g_cos[pos * 32 + fi];
        float sn = g_sin[pos * 32 + fi];
        if (seg == 0) { v0 *= 0.125f; v1 *= 0.125f; }  // DIM_HEAD^-0.5
        float o0 = v0 * cs - v1 * sn;
        float o1 = v1 * cs + v0 * sn;
        float* dst = (seg == 0) ? g_Q : g_K;
        *(float2*)(dst + p) = make_float2(o0, o1);
    }
}

// ---------------- tf32 mma.sync GEMM ---------------------------------------
// C[M,N] = A[M,512] * B[512,N], 128x128 block tile, BK=32, 8 warps (2x4),
// warp tile 64x32 of m16n8k8.
// FUSED=1: A = x, B = [w_q | w_kv], epilogue = rope/scale scatter to Q/K/V
// FUSED=0: A = g_AO, B = w_out, plain store to Cout
template <int FUSED>
__global__ __launch_bounds__(256) void gemm_kernel(
    const float* __restrict__ A,
    const float* __restrict__ B0,
    const float* __restrict__ B1,
    float* __restrict__ Cout)
{
    __shared__ uint32_t As[128][33];   // tf32 bits, m-major, pad 1
    __shared__ uint32_t Bs[32][129];   // tf32 bits, k-major, pad 1

    const int tid = threadIdx.x;
    const int warp = tid >> 5, lane = tid & 31;
    const int warpM = warp >> 2, warpN = warp & 3;
    const int grp = lane >> 2, tig = lane & 3;

    const int rowBase = blockIdx.y * 128;
    const int bx = blockIdx.x;

    const float* Bptr;
    int ldB, nb;
    if (FUSED) {
        if (bx < 4) { Bptr = B0; ldB = 512;  nb = bx * 128; }          // w_q
        else        { Bptr = B1; ldB = 1024; nb = bx * 128 - 512; }    // w_kv
    } else {
        Bptr = B0; ldB = 512; nb = bx * 128;
    }
    const float* Aptr = FUSED ? A : g_AO;

    int aRow[4], aC[4], bRow[4], bC[4];
#pragma unroll
    for (int i = 0; i < 4; i++) {
        int idx = tid + i * 256;
        aRow[i] = idx >> 3; aC[i] = (idx & 7) * 4;    // 128 x 32 tile
        bRow[i] = idx >> 5; bC[i] = (idx & 31) * 4;   // 32 x 128 tile
    }

    float4 aReg[4], bReg[4];
#pragma unroll
    for (int i = 0; i < 4; i++) {
        aReg[i] = *(const float4*)(Aptr + (size_t)(rowBase + aRow[i]) * 512 + aC[i]);
        bReg[i] = *(const float4*)(Bptr + (size_t)bRow[i] * ldB + nb + bC[i]);
    }

    float acc[4][4][4];
#pragma unroll
    for (int a = 0; a < 4; a++)
#pragma unroll
        for (int b = 0; b < 4; b++)
#pragma unroll
            for (int c = 0; c < 4; c++) acc[a][b][c] = 0.0f;

    for (int kt = 0; kt < 16; kt++) {
        // stage regs -> smem (with tf32 rounding)
#pragma unroll
        for (int i = 0; i < 4; i++) {
            As[aRow[i]][aC[i] + 0] = f2tf32(aReg[i].x);
            As[aRow[i]][aC[i] + 1] = f2tf32(aReg[i].y);
            As[aRow[i]][aC[i] + 2] = f2tf32(aReg[i].z);
            As[aRow[i]][aC[i] + 3] = f2tf32(aReg[i].w);
            Bs[bRow[i]][bC[i] + 0] = f2tf32(bReg[i].x);
            Bs[bRow[i]][bC[i] + 1] = f2tf32(bReg[i].y);
            Bs[bRow[i]][bC[i] + 2] = f2tf32(bReg[i].z);
            Bs[bRow[i]][bC[i] + 3] = f2tf32(bReg[i].w);
        }
        __syncthreads();

        if (kt < 15) {
            int k0 = (kt + 1) * 32;
#pragma unroll
            for (int i = 0; i < 4; i++) {
                aReg[i] = *(const float4*)(Aptr + (size_t)(rowBase + aRow[i]) * 512 + k0 + aC[i]);
                bReg[i] = *(const float4*)(Bptr + (size_t)(k0 + bRow[i]) * ldB + nb + bC[i]);
            }
        }

#pragma unroll
        for (int ks = 0; ks < 4; ks++) {
            const int k0 = ks * 8;
            uint32_t bf[4][2];
#pragma unroll
            for (int nf = 0; nf < 4; nf++) {
                int nc = warpN * 32 + nf * 8 + grp;
                bf[nf][0] = Bs[k0 + tig][nc];
                bf[nf][1] = Bs[k0 + tig + 4][nc];
            }
#pragma unroll
            for (int mf = 0; mf < 4; mf++) {
                int mr = warpM * 64 + mf * 16 + grp;
                uint32_t a0 = As[mr][k0 + tig];
                uint32_t a1 = As[mr + 8][k0 + tig];
                uint32_t a2 = As[mr][k0 + tig + 4];
                uint32_t a3 = As[mr + 8][k0 + tig + 4];
#pragma unroll
                for (int nf = 0; nf < 4; nf++) {
                    asm volatile(
                        "mma.sync.aligned.m16n8k8.row.col.f32.tf32.tf32.f32 "
                        "{%0,%1,%2,%3}, {%4,%5,%6,%7}, {%8,%9}, {%0,%1,%2,%3};\n"
                        : "+f"(acc[mf][nf][0]), "+f"(acc[mf][nf][1]),
                          "+f"(acc[mf][nf][2]), "+f"(acc[mf][nf][3])
                        : "r"(a0), "r"(a1), "r"(a2), "r"(a3),
                          "r"(bf[nf][0]), "r"(bf[nf][1]));
                }
            }
        }
        __syncthreads();
    }

    // -------- epilogue --------
    const int cBase = bx * 128 + warpN * 32;
#pragma unroll
    for (int mf = 0; mf < 4; mf++) {
        int r = rowBase + warpM * 64 + mf * 16 + grp;
#pragma unroll
        for (int nf = 0; nf < 4; nf++) {
            int c = cBase + nf * 8 + 2 * tig;
            if (FUSED) {
                epi_store(r,     c, acc[mf][nf][0], acc[mf][nf][1]);
                epi_store(r + 8, c, acc[mf][nf][2], acc[mf][nf][3]);
            } else {
                *(float2*)(Cout + (size_t)r * 512 + c) =
                    make_float2(acc[mf][nf][0], acc[mf][nf][1]);
                *(float2*)(Cout + (size_t)(r + 8) * 512 + c) =
                    make_float2(acc[mf][nf][2], acc[mf][nf][3]);
            }
        }
    }
}

// ---------------- attention: one block per (b,s,h) --------------------------
__global__ __launch_bounds__(256) void attn_kernel(
    const float* __restrict__ pos_bias)
{
    const int blk = blockIdx.x;        // 16384 = 2*1024*8
    const int h = blk & 7;
    const int bs = blk >> 3;           // b*1024 + s
    const int b = bs >> 10;
    const int r0 = bs * 32;
    const int tid = threadIdx.x;
    const int hc = h * 64;

    if (g_mask[b]) {
        // masked softmax over only the diagonal -> attn = I -> out = v exactly
#pragma unroll
        for (int i = 0; i < 2; i++) {
            int idx = tid + i * 256;                 // 512 float4s
            int row = idx >> 4, c4 = (idx & 15) * 4;
            size_t p = (size_t)(r0 + row) * 512 + hc + c4;
            *(float4*)(g_AO + p) = *(const float4*)(g_V + p);
        }
        return;
    }

    __shared__ float sQ[32][68], sK[32][68], sV[32][68], sS[32][33];

#pragma unroll
    for (int i = 0; i < 2; i++) {
        int idx = tid + i * 256;
        int row = idx >> 4, c4 = (idx & 15) * 4;
        size_t p = (size_t)(r0 + row) * 512 + hc + c4;
        *(float4*)&sQ[row][c4] = *(const float4*)(g_Q + p);
        *(float4*)&sK[row][c4] = *(const float4*)(g_K + p);
        *(float4*)&sV[row][c4] = *(const float4*)(g_V + p);
    }
    __syncthreads();

    // sim[i][j] = q_i . k_j + pos_bias[h,i,j] ; thread -> row i, 4 j's
    const int i = tid >> 3;
    const int jb = (tid & 7) * 4;
    float s0 = 0.f, s1 = 0.f, s2 = 0.f, s3 = 0.f;
#pragma unroll
    for (int d = 0; d < 64; d++) {
        float qv = sQ[i][d];
        s0 += qv * sK[jb + 0][d];
        s1 += qv * sK[jb + 1][d];
        s2 += qv * sK[jb + 2][d];
        s3 += qv * sK[jb + 3][d];
    }
    const float* pb = pos_bias + (size_t)h * 1024 + i * 32 + jb;
    sS[i][jb + 0] = s0 + pb[0];
    sS[i][jb + 1] = s1 + pb[1];
    sS[i][jb + 2] = s2 + pb[2];
    sS[i][jb + 3] = s3 + pb[3];
    __syncthreads();

    // softmax: warp w handles rows 4w..4w+3, one lane per column
    const int warp = tid >> 5, lane = tid & 31;
#pragma unroll
    for (int rr = 0; rr < 4; rr++) {
        int row = warp * 4 + rr;
        float v = sS[row][lane];
        float m = v;
#pragma unroll
        for (int o = 16; o > 0; o >>= 1) m = fmaxf(m, __shfl_xor_sync(0xffffffffu, m, o));
        float e = expf(v - m);
        float sum = e;
#pragma unroll
        for (int o = 16; o > 0; o >>= 1) sum += __shfl_xor_sync(0xffffffffu, sum, o);
        sS[row][lane] = e / sum;
    }
    __syncthreads();

    // out[i][d] = sum_j attn[i][j] * v[j][d]; thread -> row i, 8 d's
    const int db = (tid & 7) * 8;
    float o[8] = {0.f, 0.f, 0.f, 0.f, 0.f, 0.f, 0.f, 0.f};
#pragma unroll
    for (int j = 0; j < 32; j++) {
        float a = sS[i][j];
#pragma unroll
        for (int dd = 0; dd < 8; dd++) o[dd] += a * sV[j][db + dd];
    }
    size_t p = (size_t)(r0 + i) * 512 + hc + db;
    *(float4*)(g_AO + p)     = make_float4(o[0], o[1], o[2], o[3]);
    *(float4*)(g_AO + p + 4) = make_float4(o[4], o[5], o[6], o[7]);
}

// ---------------- launch -----------------------------------------------------
// Inputs are resolved by element count (robust to metadata ordering):
//   x=33554432, pos_bias=8192, focus=2, w_kv=524288, inv_freq=32,
//   w_q/w_out both 262144 -> disambiguated by position relative to w_kv:
//   insertion order has w_q BEFORE w_kv; sorted order puts w_out before w_q
//   (both after w_kv).
extern "C" void kernel_launch(void* const* d_in, const int* in_sizes, int n_in,
                              void* d_out, int out_size)
{
    (void)out_size;
    int ix = -1, ipb = -1, ifoc = -1, ikv = -1, iif = -1;
    int i262[2] = {-1, -1}; int n262 = 0;
    for (int i = 0; i < n_in; i++) {
        switch (in_sizes[i]) {
            case 33554432: ix = i; break;
            case 8192:     ipb = i; break;
            case 2:        ifoc = i; break;
            case 524288:   ikv = i; break;
            case 32:       iif = i; break;
            case 262144:   if (n262 < 2) i262[n262++] = i; break;
            default: break;
        }
    }
    int iq, io;
    if (n262 == 2 && i262[0] < ikv) { iq = i262[0]; io = i262[1]; }
    else                            { io = i262[0]; iq = i262[1]; }

    const float* x        = (const float*)d_in[ix];
    const float* pos_bias = (const float*)d_in[ipb];
    const uint32_t* mask  = (const uint32_t*)d_in[ifoc];
    const float* w_q      = (const float*)d_in[iq];
    const float* w_kv     = (const float*)d_in[ikv];
    const float* w_out    = (const float*)d_in[io];
    const float* inv_freq = (const float*)d_in[iif];
    float* out = (float*)d_out;

    mask_norm_kernel<<<1, 1>>>(mask);
    rope_table_kernel<<<1, 1024>>>(inv_freq);
    gemm_kernel<1><<<dim3(12, 512), 256>>>(x, w_q, w_kv, nullptr);
    attn_kernel<<<16384, 256>>>(pos_bias);
    gemm_kernel<0><<<dim3(4, 512), 256>>>(nullptr, w_out, nullptr, out);
}

// round 4
// speedup vs baseline: 1.2788x; 1.2788x over previous
#include <cuda_runtime.h>
#include <cstdint>

// Problem dims (fixed):
//  x: (2,1024,32,512) -> M = 65536 rows of K=512
//  QKV cols = 1536 (Q 0-511, K 512-1023, V 1024-1535), out proj N=512
#define M_TOTAL 65536

// ---------------- scratch (device globals; no runtime allocation) ----------
__device__ float g_Q[(size_t)M_TOTAL * 512];
__device__ float g_K[(size_t)M_TOTAL * 512];
__device__ float g_V[(size_t)M_TOTAL * 512];
__device__ float g_AO[(size_t)M_TOTAL * 512];
__device__ float g_cos[1024];
__device__ float g_sin[1024];
__device__ int   g_mask[2];

// ---------------- helpers ----------------------------------------------------
__device__ __forceinline__ uint32_t f2tf32(float x) {
    uint32_t r;
    asm("cvt.rna.tf32.f32 %0, %1;" : "=r"(r) : "f"(x));
    return r;
}

__global__ void mask_norm_kernel(const uint32_t* __restrict__ m) {
    uint32_t w0 = m[0], w1 = m[1];
    if (w0 <= 1u && w1 <= 1u) {
        g_mask[0] = (int)w0; g_mask[1] = (int)w1;
    } else {
        const unsigned char* p = (const unsigned char*)m;
        g_mask[0] = p[0] ? 1 : 0; g_mask[1] = p[1] ? 1 : 0;
    }
}
__global__ void rope_table_kernel(const float* __restrict__ inv_freq) {
    int t = threadIdx.x;           // 1024 threads: pos(32) x freq(32)
    float ang = (float)(t >> 5) * inv_freq[t & 31];
    g_cos[t] = cosf(ang);
    g_sin[t] = sinf(ang);
}

// Epilogue store for the fused QKV GEMM (c in [0,1536)).
__device__ __forceinline__ void epi_store(int r, int c, float v0, float v1) {
    int seg = c >> 9;
    int off = c & 511;
    size_t p = (size_t)r * 512 + off;
    if (seg == 2) {
        *(float2*)(g_V + p) = make_float2(v0, v1);
    } else {
        int pos = r & 31;
        int fi = (c & 63) >> 1;
        float cs = g_cos[pos * 32 + fi];
        float sn = g_sin[pos * 32 + fi];
        if (seg == 0) { v0 *= 0.125f; v1 *= 0.125f; }
        float o0 = v0 * cs - v1 * sn;
        float o1 = v1 * cs + v0 * sn;
        float* dst = (seg == 0) ? g_Q : g_K;
        *(float2*)(dst + p) = make_float2(o0, o1);
    }
}

// ---------------- tf32 mma.sync GEMM, double-buffered, conflict-free --------
// C[M,N] = A[M,512]*B[512,N]; block 128x128, BK=32, 8 warps (2x4), warp 64x32.
// smem word layout (dynamic):
//   As[s]: A(m,k) at m*36 + k      (rows 36 words; frag banks 4*grp+tig: CF)
//   Bs[s]: B(k,n) at k*136 + n     (rows 136 words; frag banks 8*tig+grp: CF)
#define AS_WORDS (128 * 36)
#define BS_WORDS (32 * 136)
#define GEMM_SMEM_BYTES ((2 * AS_WORDS + 2 * BS_WORDS) * 4)

template <int FUSED>
__global__ __launch_bounds__(256, 1) void gemm_kernel(
    const float* __restrict__ A,
    const float* __restrict__ B0,
    const float* __restrict__ B1,
    float* __restrict__ Cout)
{
    extern __shared__ uint32_t sw[];
    uint32_t* const Asm[2] = { sw, sw + AS_WORDS };
    uint32_t* const Bsm[2] = { sw + 2 * AS_WORDS, sw + 2 * AS_WORDS + BS_WORDS };

    const int tid = threadIdx.x;
    const int warp = tid >> 5, lane = tid & 31;
    const int wm = (warp >> 2) * 64, wn = (warp & 3) * 32;
    const int grp = lane >> 2, tig = lane & 3;
    const int rowBase = blockIdx.y * 128;
    const int bx = blockIdx.x;

    const float* Bp; int ldB, nb;
    if (FUSED) {
        if (bx < 4) { Bp = B0; ldB = 512;  nb = bx * 128; }          // w_q
        else        { Bp = B1; ldB = 1024; nb = bx * 128 - 512; }    // w_kv
    } else { Bp = B0; ldB = 512; nb = bx * 128; }
    const float* Ap = FUSED ? A : g_AO;

    float4 ra[4], rb[4];
    auto LOADG = [&](int c) {
        const int k0 = c * 32;
#pragma unroll
        for (int i = 0; i < 4; i++) {
            int lin = tid + 256 * i;
            ra[i] = *(const float4*)(Ap + (size_t)(rowBase + (lin >> 3)) * 512 + k0 + (lin & 7) * 4);
            rb[i] = *(const float4*)(Bp + (size_t)(k0 + (lin >> 5)) * ldB + nb + (lin & 31) * 4);
        }
    };
    auto STORE = [&](int s) {
        uint32_t* as = Asm[s];
        uint32_t* bs = Bsm[s];
#pragma unroll
        for (int i = 0; i < 4; i++) {
            int lin = tid + 256 * i;
            *(uint4*)&as[(lin >> 3) * 36 + (lin & 7) * 4] =
                make_uint4(f2tf32(ra[i].x), f2tf32(ra[i].y), f2tf32(ra[i].z), f2tf32(ra[i].w));
            *(uint4*)&bs[(lin >> 5) * 136 + (lin & 31) * 4] =
                make_uint4(f2tf32(rb[i].x), f2tf32(rb[i].y), f2tf32(rb[i].z), f2tf32(rb[i].w));
        }
    };

    uint32_t af[2][4][4], bf[2][4][2];
    auto LOADFRAG = [&](int s, int ks, int buf) {
        const int k0 = ks * 8;
        const uint32_t* as = Asm[s];
        const uint32_t* bs = Bsm[s];
#pragma unroll
        for (int mf = 0; mf < 4; mf++) {
            const uint32_t* p = &as[(wm + mf * 16 + grp) * 36 + k0 + tig];
            af[buf][mf][0] = p[0];
            af[buf][mf][1] = p[8 * 36];
            af[buf][mf][2] = p[4];
            af[buf][mf][3] = p[8 * 36 + 4];
        }
#pragma unroll
        for (int nf = 0; nf < 4; nf++) {
            int nc = wn + nf * 8 + grp;
            bf[buf][nf][0] = bs[(k0 + tig) * 136 + nc];
            bf[buf][nf][1] = bs[(k0 + tig + 4) * 136 + nc];
        }
    };

    float acc[4][4][4];
#pragma unroll
    for (int a = 0; a < 4; a++)
#pragma unroll
        for (int b = 0; b < 4; b++)
#pragma unroll
            for (int c = 0; c < 4; c++) acc[a][b][c] = 0.0f;

    LOADG(0);
    STORE(0);
    __syncthreads();

#pragma unroll 1
    for (int c = 0; c < 16; c++) {
        const int s = c & 1;
        if (c < 15) LOADG(c + 1);
        LOADFRAG(s, 0, 0);
#pragma unroll
        for (int ks = 0; ks < 4; ks++) {
            const int cur = ks & 1;
            if (ks < 3) LOADFRAG(s, ks + 1, cur ^ 1);
#pragma unroll
            for (int mf = 0; mf < 4; mf++)
#pragma unroll
                for (int nf = 0; nf < 4; nf++) {
                    asm volatile(
                        "mma.sync.aligned.m16n8k8.row.col.f32.tf32.tf32.f32 "
                        "{%0,%1,%2,%3}, {%4,%5,%6,%7}, {%8,%9}, {%0,%1,%2,%3};\n"
                        : "+f"(acc[mf][nf][0]), "+f"(acc[mf][nf][1]),
                          "+f"(acc[mf][nf][2]), "+f"(acc[mf][nf][3])
                        : "r"(af[cur][mf][0]), "r"(af[cur][mf][1]),
                          "r"(af[cur][mf][2]), "r"(af[cur][mf][3]),
                          "r"(bf[cur][nf][0]), "r"(bf[cur][nf][1]));
                }
        }
        if (c < 15) {
            STORE(s ^ 1);
            __syncthreads();
        }
    }

    // -------- epilogue --------
    const int cBase = bx * 128 + wn;
#pragma unroll
    for (int mf = 0; mf < 4; mf++) {
        int r = rowBase + wm + mf * 16 + grp;
#pragma unroll
        for (int nf = 0; nf < 4; nf++) {
            int c = cBase + nf * 8 + 2 * tig;
            if (FUSED) {
                epi_store(r,     c, acc[mf][nf][0], acc[mf][nf][1]);
                epi_store(r + 8, c, acc[mf][nf][2], acc[mf][nf][3]);
            } else {
                *(float2*)(Cout + (size_t)r * 512 + c) =
                    make_float2(acc[mf][nf][0], acc[mf][nf][1]);
                *(float2*)(Cout + (size_t)(r + 8) * 512 + c) =
                    make_float2(acc[mf][nf][2], acc[mf][nf][3]);
            }
        }
    }
}

// ---------------- attention: one block per (b,s,h) --------------------------
// sQ/sK row stride 65 words (odd) -> scalar fragment reads conflict-free
// (8 distinct banks x 4-lane broadcast). sV stride 72 keeps float4 alignment.
__global__ __launch_bounds__(256) void attn_kernel(const float* __restrict__ pos_bias)
{
    const int blk = blockIdx.x;        // 16384 = 2*1024*8
    const int h = blk & 7;
    const int bs = blk >> 3;
    const int b = bs >> 10;
    const int r0 = bs * 32;
    const int tid = threadIdx.x;
    const int hc = h * 64;

    if (g_mask[b]) {
        // masked softmax over only the diagonal -> attn = I -> out = v exactly
#pragma unroll
        for (int i = 0; i < 2; i++) {
            int idx = tid + i * 256;
            int row = idx >> 4, c4 = (idx & 15) * 4;
            size_t p = (size_t)(r0 + row) * 512 + hc + c4;
            *(float4*)(g_AO + p) = *(const float4*)(g_V + p);
        }
        return;
    }

    __shared__ float sQ[32][65];
    __shared__ float sK[32][65];
    __shared__ float sV[32][72];
    __shared__ float sS[32][33];

#pragma unroll
    for (int i = 0; i < 2; i++) {
        int idx = tid + i * 256;
        int row = idx >> 4, c4 = (idx & 15) * 4;
        size_t p = (size_t)(r0 + row) * 512 + hc + c4;
        float4 q = *(const float4*)(g_Q + p);
        float4 k = *(const float4*)(g_K + p);
        float4 v = *(const float4*)(g_V + p);
        sQ[row][c4 + 0] = q.x; sQ[row][c4 + 1] = q.y;
        sQ[row][c4 + 2] = q.z; sQ[row][c4 + 3] = q.w;
        sK[row][c4 + 0] = k.x; sK[row][c4 + 1] = k.y;
        sK[row][c4 + 2] = k.z; sK[row][c4 + 3] = k.w;
        *(float4*)&sV[row][c4] = v;
    }
    __syncthreads();

    // sim[i][j] = q_i . k_j + pos_bias; thread -> (row i, 4 j's)
    const int i = tid >> 3;
    const int jb = (tid & 7) * 4;
    float s0 = 0.f, s1 = 0.f, s2 = 0.f, s3 = 0.f;
#pragma unroll
    for (int d = 0; d < 64; d++) {
        float qv = sQ[i][d];
        s0 += qv * sK[jb + 0][d];
        s1 += qv * sK[jb + 1][d];
        s2 += qv * sK[jb + 2][d];
        s3 += qv * sK[jb + 3][d];
    }
    float4 pb = *(const float4*)(pos_bias + (size_t)h * 1024 + i * 32 + jb);
    sS[i][jb + 0] = s0 + pb.x;
    sS[i][jb + 1] = s1 + pb.y;
    sS[i][jb + 2] = s2 + pb.z;
    sS[i][jb + 3] = s3 + pb.w;
    __syncthreads();

    // softmax: warp w -> rows 4w..4w+3, one lane per column
    const int warp = tid >> 5, lane = tid & 31;
#pragma unroll
    for (int rr = 0; rr < 4; rr++) {
        int row = warp * 4 + rr;
        float v = sS[row][lane];
        float m = v;
#pragma unroll
        for (int o = 16; o > 0; o >>= 1) m = fmaxf(m, __shfl_xor_sync(0xffffffffu, m, o));
        float e = expf(v - m);
        float sum = e;
#pragma unroll
        for (int o = 16; o > 0; o >>= 1) sum += __shfl_xor_sync(0xffffffffu, sum, o);
        sS[row][lane] = e / sum;
    }
    __syncthreads();

    // out[i][d] = sum_j attn[i][j] * v[j][d]; thread -> (row i, 8 d's)
    const int db = (tid & 7) * 8;
    float4 o0 = make_float4(0.f, 0.f, 0.f, 0.f);
    float4 o1 = make_float4(0.f, 0.f, 0.f, 0.f);
#pragma unroll
    for (int j = 0; j < 32; j++) {
        float a = sS[i][j];
        float4 v0 = *(const float4*)&sV[j][db];
        float4 v1 = *(const float4*)&sV[j][db + 4];
        o0.x += a * v0.x; o0.y += a * v0.y; o0.z += a * v0.z; o0.w += a * v0.w;
        o1.x += a * v1.x; o1.y += a * v1.y; o1.z += a * v1.z; o1.w += a * v1.w;
    }
    size_t p = (size_t)(r0 + i) * 512 + hc + db;
    *(float4*)(g_AO + p)     = o0;
    *(float4*)(g_AO + p + 4) = o1;
}

// ---------------- launch ------------------------------------------------------
// Inputs resolved by element count (robust to metadata ordering); w_q vs w_out
// (both 262144) disambiguated by position relative to w_kv.
extern "C" void kernel_launch(void* const* d_in, const int* in_sizes, int n_in,
                              void* d_out, int out_size)
{
    (void)out_size;
    int ix = -1, ipb = -1, ifoc = -1, ikv = -1, iif = -1;
    int i262[2] = {-1, -1}; int n262 = 0;
    for (int i = 0; i < n_in; i++) {
        switch (in_sizes[i]) {
            case 33554432: ix = i; break;
            case 8192:     ipb = i; break;
            case 2:        ifoc = i; break;
            case 524288:   ikv = i; break;
            case 32:       iif = i; break;
            case 262144:   if (n262 < 2) i262[n262++] = i; break;
            default: break;
        }
    }
    int iq, io;
    if (n262 == 2 && i262[0] < ikv) { iq = i262[0]; io = i262[1]; }
    else                            { io = i262[0]; iq = i262[1]; }

    const float* x        = (const float*)d_in[ix];
    const float* pos_bias = (const float*)d_in[ipb];
    const uint32_t* mask  = (const uint32_t*)d_in[ifoc];
    const float* w_q      = (const float*)d_in[iq];
    const float* w_kv     = (const float*)d_in[ikv];
    const float* w_out    = (const float*)d_in[io];
    const float* inv_freq = (const float*)d_in[iif];
    float* out = (float*)d_out;

    cudaFuncSetAttribute(gemm_kernel<1>, cudaFuncAttributeMaxDynamicSharedMemorySize, GEMM_SMEM_BYTES);
    cudaFuncSetAttribute(gemm_kernel<0>, cudaFuncAttributeMaxDynamicSharedMemorySize, GEMM_SMEM_BYTES);

    mask_norm_kernel<<<1, 1>>>(mask);
    rope_table_kernel<<<1, 1024>>>(inv_freq);
    gemm_kernel<1><<<dim3(12, 512), 256, GEMM_SMEM_BYTES>>>(x, w_q, w_kv, nullptr);
    attn_kernel<<<16384, 256>>>(pos_bias);
    gemm_kernel<0><<<dim3(4, 512), 256, GEMM_SMEM_BYTES>>>(nullptr, w_out, nullptr, out);
}

// round 6
// speedup vs baseline: 2.0781x; 1.6250x over previous
#include <cuda_runtime.h>
#include <cuda_fp16.h>
#include <cstdint>

// Problem dims (fixed):
//  x: (2,1024,32,512) -> M = 65536 rows of K=512
//  QKV cols = 1536 (Q 0-511, K 512-1023, V 1024-1535), out proj N=512
#define M_TOTAL 65536

// ---------------- scratch (device globals; no runtime allocation) ----------
__device__ float    g_Q[(size_t)M_TOTAL * 512];
__device__ float    g_K[(size_t)M_TOTAL * 512];
__device__ float    g_V[(size_t)M_TOTAL * 512];
__device__ uint32_t g_Xp[(size_t)M_TOTAL * 256];    // x as half2 pairs along k
__device__ uint32_t g_AOp[(size_t)M_TOTAL * 256];   // attn out as half2 pairs
__device__ uint32_t g_WQKVp[256 * 1536];            // [k2][n] half2(w[2k2][n], w[2k2+1][n])
__device__ uint32_t g_WOp[256 * 512];
__device__ float    g_cos[1024];
__device__ float    g_sin[1024];
__device__ int      g_mask[2];

// ---------------- helpers ----------------------------------------------------
__device__ __forceinline__ uint32_t packh2(float lo, float hi) {
    __half2 h = __floats2half2_rn(lo, hi);
    return *reinterpret_cast<uint32_t*>(&h);
}
__device__ __forceinline__ uint32_t smem_u32(const void* p) {
    uint32_t a;
    asm("{ .reg .u64 t; cvta.to.shared.u64 t, %1; cvt.u32.u64 %0, t; }"
        : "=r"(a) : "l"(p));
    return a;
}
__device__ __forceinline__ void cp16(uint32_t dst, const void* src) {
    asm volatile("cp.async.cg.shared.global [%0], [%1], 16;"
                 :: "r"(dst), "l"(src) : "memory");
}
__device__ __forceinline__ void cp_commit() {
    asm volatile("cp.async.commit_group;" ::: "memory");
}
__device__ __forceinline__ void cp_wait_all() {
    asm volatile("cp.async.wait_group 0;" ::: "memory");
}

// ---------------- setup: pack x/weights to fp16, rope table, mask -----------
__global__ void setup_kernel(
    const float* __restrict__ x,
    const float* __restrict__ w_q,
    const float* __restrict__ w_kv,
    const float* __restrict__ w_out,
    const float* __restrict__ inv_freq,
    const uint32_t* __restrict__ m)
{
    const int bid = blockIdx.x;
    if (bid < 16384) {
        // x: 16777216 half2 words; 16384 blocks x 256 thr x 4 words
        size_t base = ((size_t)bid * 256 + threadIdx.x) * 4;
#pragma unroll
        for (int j = 0; j < 4; j++) {
            size_t w = base + j;
            float2 v = *(const float2*)(x + 2 * w);
            g_Xp[w] = packh2(v.x, v.y);
        }
    } else if (bid < 16384 + 512) {
        // weights: 393216 (qkv) + 131072 (out) = 524288 words
        size_t base = ((size_t)(bid - 16384) * 256 + threadIdx.x) * 4;
#pragma unroll
        for (int j = 0; j < 4; j++) {
            size_t w = base + j;
            if (w < 393216) {
                int k2 = (int)(w / 1536), n = (int)(w % 1536);
                float a, b;
                if (n < 512) {
                    a = w_q[(size_t)(2 * k2) * 512 + n];
                    b = w_q[(size_t)(2 * k2 + 1) * 512 + n];
                } else {
                    int nn = n - 512;
                    a = w_kv[(size_t)(2 * k2) * 1024 + nn];
                    b = w_kv[(size_t)(2 * k2 + 1) * 1024 + nn];
                }
                g_WQKVp[w] = packh2(a, b);
            } else {
                size_t w2 = w - 393216;
                int k2 = (int)(w2 / 512), n = (int)(w2 % 512);
                g_WOp[w2] = packh2(w_out[(size_t)(2 * k2) * 512 + n],
                                   w_out[(size_t)(2 * k2 + 1) * 512 + n]);
            }
        }
    } else {
        // rope table (1024 entries) + mask
#pragma unroll
        for (int j = 0; j < 4; j++) {
            int t = threadIdx.x * 4 + j;
            float ang = (float)(t >> 5) * inv_freq[t & 31];
            g_cos[t] = cosf(ang);
            g_sin[t] = sinf(ang);
        }
        if (threadIdx.x == 0) {
            uint32_t w0 = m[0], w1 = m[1];
            if (w0 <= 1u && w1 <= 1u) {
                g_mask[0] = (int)w0; g_mask[1] = (int)w1;
            } else {
                const unsigned char* p = (const unsigned char*)m;
                g_mask[0] = p[0] ? 1 : 0; g_mask[1] = p[1] ? 1 : 0;
            }
        }
    }
}

// Epilogue store for the fused QKV GEMM (c in [0,1536)).
__device__ __forceinline__ void epi_store(int r, int c, float v0, float v1) {
    int seg = c >> 9;
    int off = c & 511;
    size_t p = (size_t)r * 512 + off;
    if (seg == 2) {
        *(float2*)(g_V + p) = make_float2(v0, v1);
    } else {
        int pos = r & 31;
        int fi = (c & 63) >> 1;
        float cs = g_cos[pos * 32 + fi];
        float sn = g_sin[pos * 32 + fi];
        if (seg == 0) { v0 *= 0.125f; v1 *= 0.125f; }
        float o0 = v0 * cs - v1 * sn;
        float o1 = v1 * cs + v0 * sn;
        float* dst = (seg == 0) ? g_Q : g_K;
        *(float2*)(dst + p) = make_float2(o0, o1);
    }
}

// ---------------- fp16 mma.sync GEMM, cp.async double-buffered ---------------
// C[M,N] = A[M,512]*B[512,N]; block 128x128, BK=32 (2 k16 steps), 8 warps
// (2x4), warp tile 64x32 of m16n8k16.
// Operand pointers are selected DEVICE-SIDE from the FUSED template param
// (device globals must not be passed as kernel args from host code).
// A smem: uint32 pairs A[m][k2], row stride 20 words (frag banks 20g+t: CF)
// B smem: uint32 pairs B[k2][n], row stride 136 words (frag banks 8t+g: CF)
#define AS_STRIDE 20
#define BS_STRIDE 136
#define AS_WORDS (128 * AS_STRIDE)   // 2560
#define BS_WORDS (16 * BS_STRIDE)    // 2176
#define STG_WORDS (AS_WORDS + BS_WORDS)

template <int FUSED>
__global__ __launch_bounds__(256, 2) void gemm_kernel(float* __restrict__ Cout)
{
    __shared__ uint32_t sw[2 * STG_WORDS];

    const uint32_t* const Apack = FUSED ? g_Xp : g_AOp;
    const uint32_t* const Bpack = FUSED ? g_WQKVp : g_WOp;

    const int tid = threadIdx.x;
    const int warp = tid >> 5, lane = tid & 31;
    const int wm = (warp >> 2) * 64, wn = (warp & 3) * 32;
    const int grp = lane >> 2, tig = lane & 3;
    const int rowBase = blockIdx.y * 128;
    const int bx = blockIdx.x;
    const int ldBp = FUSED ? 1536 : 512;
    const int nb = bx * 128;
    const uint32_t sbase = smem_u32(sw);

    auto ISSUE = [&](int c, int s) {
        const uint32_t stg = sbase + (uint32_t)s * STG_WORDS * 4;
        // A: 512 cp16 ops (128 rows x 16 words)
#pragma unroll
        for (int i = 0; i < 2; i++) {
            int op = tid + 256 * i;
            int row = op >> 2, c4 = (op & 3) * 4;
            cp16(stg + (uint32_t)(row * AS_STRIDE + c4) * 4,
                 Apack + (size_t)(rowBase + row) * 256 + c * 16 + c4);
        }
        // B: 512 cp16 ops (16 k2-rows x 128 words)
#pragma unroll
        for (int i = 0; i < 2; i++) {
            int op = tid + 256 * i;
            int r = op >> 5, n4 = (op & 31) * 4;
            cp16(stg + (uint32_t)(AS_WORDS + r * BS_STRIDE + n4) * 4,
                 Bpack + (size_t)(c * 16 + r) * ldBp + nb + n4);
        }
    };

    uint32_t af[4][4], bf[4][2];
    auto LOADFRAG = [&](int s, int ks) {
        const uint32_t* as = sw + s * STG_WORDS;
        const uint32_t* bs = as + AS_WORDS;
        const int k0 = ks * 8;
#pragma unroll
        for (int mf = 0; mf < 4; mf++) {
            const uint32_t* p = &as[(wm + mf * 16 + grp) * AS_STRIDE + k0 + tig];
            af[mf][0] = p[0];
            af[mf][1] = p[8 * AS_STRIDE];
            af[mf][2] = p[4];
            af[mf][3] = p[8 * AS_STRIDE + 4];
        }
#pragma unroll
        for (int nf = 0; nf < 4; nf++) {
            int nc = wn + nf * 8 + grp;
            bf[nf][0] = bs[(k0 + tig) * BS_STRIDE + nc];
            bf[nf][1] = bs[(k0 + tig + 4) * BS_STRIDE + nc];
        }
    };

    float acc[4][4][4];
#pragma unroll
    for (int a = 0; a < 4; a++)
#pragma unroll
        for (int b = 0; b < 4; b++)
#pragma unroll
            for (int c = 0; c < 4; c++) acc[a][b][c] = 0.0f;

    ISSUE(0, 0);
    cp_commit();

#pragma unroll 1
    for (int c = 0; c < 16; c++) {
        const int s = c & 1;
        cp_wait_all();
        __syncthreads();
        if (c < 15) { ISSUE(c + 1, s ^ 1); cp_commit(); }
#pragma unroll
        for (int ks = 0; ks < 2; ks++) {
            LOADFRAG(s, ks);
#pragma unroll
            for (int mf = 0; mf < 4; mf++)
#pragma unroll
                for (int nf = 0; nf < 4; nf++) {
                    asm volatile(
                        "mma.sync.aligned.m16n8k16.row.col.f32.f16.f16.f32 "
                        "{%0,%1,%2,%3}, {%4,%5,%6,%7}, {%8,%9}, {%0,%1,%2,%3};\n"
                        : "+f"(acc[mf][nf][0]), "+f"(acc[mf][nf][1]),
                          "+f"(acc[mf][nf][2]), "+f"(acc[mf][nf][3])
                        : "r"(af[mf][0]), "r"(af[mf][1]),
                          "r"(af[mf][2]), "r"(af[mf][3]),
                          "r"(bf[nf][0]), "r"(bf[nf][1]));
                }
        }
    }

    // -------- epilogue --------
    const int cBase = bx * 128 + wn;
#pragma unroll
    for (int mf = 0; mf < 4; mf++) {
        int r = rowBase + wm + mf * 16 + grp;
#pragma unroll
        for (int nf = 0; nf < 4; nf++) {
            int c = cBase + nf * 8 + 2 * tig;
            if (FUSED) {
                epi_store(r,     c, acc[mf][nf][0], acc[mf][nf][1]);
                epi_store(r + 8, c, acc[mf][nf][2], acc[mf][nf][3]);
            } else {
                *(float2*)(Cout + (size_t)r * 512 + c) =
                    make_float2(acc[mf][nf][0], acc[mf][nf][1]);
                *(float2*)(Cout + (size_t)(r + 8) * 512 + c) =
                    make_float2(acc[mf][nf][2], acc[mf][nf][3]);
            }
        }
    }
}

// ---------------- attention: one block per (b,s,h) --------------------------
// Output written as packed half2 pairs (g_AOp) to feed gemm2 directly.
__global__ __launch_bounds__(256) void attn_kernel(const float* __restrict__ pos_bias)
{
    const int blk = blockIdx.x;        // 16384 = 2*1024*8
    const int h = blk & 7;
    const int bs = blk >> 3;
    const int b = bs >> 10;
    const int r0 = bs * 32;
    const int tid = threadIdx.x;
    const int hc = h * 64;

    if (g_mask[b]) {
        // masked softmax over only the diagonal -> attn = I -> out = v exactly
#pragma unroll
        for (int i = 0; i < 2; i++) {
            int idx = tid + i * 256;
            int row = idx >> 4, c4 = (idx & 15) * 4;
            float4 v = *(const float4*)(g_V + (size_t)(r0 + row) * 512 + hc + c4);
            uint2 w = make_uint2(packh2(v.x, v.y), packh2(v.z, v.w));
            *(uint2*)&g_AOp[(size_t)(r0 + row) * 256 + ((hc + c4) >> 1)] = w;
        }
        return;
    }

    __shared__ float sQ[32][65];
    __shared__ float sK[32][65];
    __shared__ float sV[32][72];
    __shared__ float sS[32][33];

#pragma unroll
    for (int i = 0; i < 2; i++) {
        int idx = tid + i * 256;
        int row = idx >> 4, c4 = (idx & 15) * 4;
        size_t p = (size_t)(r0 + row) * 512 + hc + c4;
        float4 q = *(const float4*)(g_Q + p);
        float4 k = *(const float4*)(g_K + p);
        float4 v = *(const float4*)(g_V + p);
        sQ[row][c4 + 0] = q.x; sQ[row][c4 + 1] = q.y;
        sQ[row][c4 + 2] = q.z; sQ[row][c4 + 3] = q.w;
        sK[row][c4 + 0] = k.x; sK[row][c4 + 1] = k.y;
        sK[row][c4 + 2] = k.z; sK[row][c4 + 3] = k.w;
        *(float4*)&sV[row][c4] = v;
    }
    __syncthreads();

    // sim[i][j] = q_i . k_j + pos_bias; thread -> (row i, 4 j's)
    const int i = tid >> 3;
    const int jb = (tid & 7) * 4;
    float s0 = 0.f, s1 = 0.f, s2 = 0.f, s3 = 0.f;
#pragma unroll
    for (int d = 0; d < 64; d++) {
        float qv = sQ[i][d];
        s0 += qv * sK[jb + 0][d];
        s1 += qv * sK[jb + 1][d];
        s2 += qv * sK[jb + 2][d];
        s3 += qv * sK[jb + 3][d];
    }
    float4 pb = *(const float4*)(pos_bias + (size_t)h * 1024 + i * 32 + jb);
    sS[i][jb + 0] = s0 + pb.x;
    sS[i][jb + 1] = s1 + pb.y;
    sS[i][jb + 2] = s2 + pb.z;
    sS[i][jb + 3] = s3 + pb.w;
    __syncthreads();

    // softmax: warp w -> rows 4w..4w+3, one lane per column
    const int warp = tid >> 5, lane = tid & 31;
#pragma unroll
    for (int rr = 0; rr < 4; rr++) {
        int row = warp * 4 + rr;
        float v = sS[row][lane];
        float m = v;
#pragma unroll
        for (int o = 16; o > 0; o >>= 1) m = fmaxf(m, __shfl_xor_sync(0xffffffffu, m, o));
        float e = expf(v - m);
        float sum = e;
#pragma unroll
        for (int o = 16; o > 0; o >>= 1) sum += __shfl_xor_sync(0xffffffffu, sum, o);
        sS[row][lane] = e / sum;
    }
    __syncthreads();

    // out[i][d] = sum_j attn[i][j] * v[j][d]; thread -> (row i, 8 d's)
    const int db = (tid & 7) * 8;
    float4 o0 = make_float4(0.f, 0.f, 0.f, 0.f);
    float4 o1 = make_float4(0.f, 0.f, 0.f, 0.f);
#pragma unroll
    for (int j = 0; j < 32; j++) {
        float a = sS[i][j];
        float4 v0 = *(const float4*)&sV[j][db];
        float4 v1 = *(const float4*)&sV[j][db + 4];
        o0.x += a * v0.x; o0.y += a * v0.y; o0.z += a * v0.z; o0.w += a * v0.w;
        o1.x += a * v1.x; o1.y += a * v1.y; o1.z += a * v1.z; o1.w += a * v1.w;
    }
    uint4 w = make_uint4(packh2(o0.x, o0.y), packh2(o0.z, o0.w),
                         packh2(o1.x, o1.y), packh2(o1.z, o1.w));
    *(uint4*)&g_AOp[(size_t)(r0 + i) * 256 + ((hc + db) >> 1)] = w;
}

// ---------------- launch ------------------------------------------------------
// Inputs resolved by element count (robust to metadata ordering); w_q vs w_out
// (both 262144) disambiguated by position relative to w_kv.
extern "C" void kernel_launch(void* const* d_in, const int* in_sizes, int n_in,
                              void* d_out, int out_size)
{
    (void)out_size;
    int ix = -1, ipb = -1, ifoc = -1, ikv = -1, iif = -1;
    int i262[2] = {-1, -1}; int n262 = 0;
    for (int i = 0; i < n_in; i++) {
        switch (in_sizes[i]) {
            case 33554432: ix = i; break;
            case 8192:     ipb = i; break;
            case 2:        ifoc = i; break;
            case 524288:   ikv = i; break;
            case 32:       iif = i; break;
            case 262144:   if (n262 < 2) i262[n262++] = i; break;
            default: break;
        }
    }
    int iq, io;
    if (n262 == 2 && i262[0] < ikv) { iq = i262[0]; io = i262[1]; }
    else                            { io = i262[0]; iq = i262[1]; }

    const float* x        = (const float*)d_in[ix];
    const float* pos_bias = (const float*)d_in[ipb];
    const uint32_t* mask  = (const uint32_t*)d_in[ifoc];
    const float* w_q      = (const float*)d_in[iq];
    const float* w_kv     = (const float*)d_in[ikv];
    const float* w_out    = (const float*)d_in[io];
    const float* inv_freq = (const float*)d_in[iif];
    float* out = (float*)d_out;

    setup_kernel<<<16384 + 512 + 1, 256>>>(x, w_q, w_kv, w_out, inv_freq, mask);
    gemm_kernel<1><<<dim3(12, 512), 256>>>(nullptr);
    attn_kernel<<<16384, 256>>>(pos_bias);
    gemm_kernel<0><<<dim3(4, 512), 256>>>(out);
}

// round 7
// speedup vs baseline: 2.1355x; 1.0276x over previous
#include <cuda_runtime.h>
#include <cuda_fp16.h>
#include <cstdint>

// Problem dims (fixed):
//  x: (2,1024,32,512) -> M = 65536 rows of K=512
//  QKV cols = 1536 (Q 0-511, K 512-1023, V 1024-1535), out proj N=512
#define M_TOTAL 65536

// ---------------- scratch (device globals; no runtime allocation) ----------
__device__ uint32_t g_Qh[(size_t)M_TOTAL * 256];    // roped+scaled Q, half2 along d
__device__ uint32_t g_Kh[(size_t)M_TOTAL * 256];    // roped K, half2 along d
__device__ uint32_t g_Vh[(size_t)M_TOTAL * 256];    // V, half2 along d
__device__ uint32_t g_Xp[(size_t)M_TOTAL * 256];    // x as half2 pairs along k
__device__ uint32_t g_AOp[(size_t)M_TOTAL * 256];   // attn out as half2 pairs
__device__ uint32_t g_WQKVp[256 * 1536];            // [k2][n] half2(w[2k2][n], w[2k2+1][n])
__device__ uint32_t g_WOp[256 * 512];
__device__ float    g_cos[1024];
__device__ float    g_sin[1024];
__device__ int      g_mask[2];

// ---------------- helpers ----------------------------------------------------
__device__ __forceinline__ uint32_t packh2(float lo, float hi) {
    __half2 h = __floats2half2_rn(lo, hi);
    return *reinterpret_cast<uint32_t*>(&h);
}
__device__ __forceinline__ float2 unpackh2(uint32_t w) {
    return __half22float2(*reinterpret_cast<__half2*>(&w));
}
__device__ __forceinline__ uint32_t smem_u32(const void* p) {
    uint32_t a;
    asm("{ .reg .u64 t; cvta.to.shared.u64 t, %1; cvt.u32.u64 %0, t; }"
        : "=r"(a) : "l"(p));
    return a;
}
__device__ __forceinline__ void cp16(uint32_t dst, const void* src) {
    asm volatile("cp.async.cg.shared.global [%0], [%1], 16;"
                 :: "r"(dst), "l"(src) : "memory");
}
__device__ __forceinline__ void cp_commit() {
    asm volatile("cp.async.commit_group;" ::: "memory");
}

// ---------------- setup: pack x/weights to fp16, rope table, mask -----------
__global__ void setup_kernel(
    const float* __restrict__ x,
    const float* __restrict__ w_q,
    const float* __restrict__ w_kv,
    const float* __restrict__ w_out,
    const float* __restrict__ inv_freq,
    const uint32_t* __restrict__ m)
{
    const int bid = blockIdx.x;
    if (bid < 16384) {
        size_t base = ((size_t)bid * 256 + threadIdx.x) * 4;
#pragma unroll
        for (int j = 0; j < 4; j++) {
            size_t w = base + j;
            float2 v = *(const float2*)(x + 2 * w);
            g_Xp[w] = packh2(v.x, v.y);
        }
    } else if (bid < 16384 + 512) {
        size_t base = ((size_t)(bid - 16384) * 256 + threadIdx.x) * 4;
#pragma unroll
        for (int j = 0; j < 4; j++) {
            size_t w = base + j;
            if (w < 393216) {
                int k2 = (int)(w / 1536), n = (int)(w % 1536);
                float a, b;
                if (n < 512) {
                    a = w_q[(size_t)(2 * k2) * 512 + n];
                    b = w_q[(size_t)(2 * k2 + 1) * 512 + n];
                } else {
                    int nn = n - 512;
                    a = w_kv[(size_t)(2 * k2) * 1024 + nn];
                    b = w_kv[(size_t)(2 * k2 + 1) * 1024 + nn];
                }
                g_WQKVp[w] = packh2(a, b);
            } else {
                size_t w2 = w - 393216;
                int k2 = (int)(w2 / 512), n = (int)(w2 % 512);
                g_WOp[w2] = packh2(w_out[(size_t)(2 * k2) * 512 + n],
                                   w_out[(size_t)(2 * k2 + 1) * 512 + n]);
            }
        }
    } else {
#pragma unroll
        for (int j = 0; j < 4; j++) {
            int t = threadIdx.x * 4 + j;
            float ang = (float)(t >> 5) * inv_freq[t & 31];
            g_cos[t] = cosf(ang);
            g_sin[t] = sinf(ang);
        }
        if (threadIdx.x == 0) {
            uint32_t w0 = m[0], w1 = m[1];
            if (w0 <= 1u && w1 <= 1u) {
                g_mask[0] = (int)w0; g_mask[1] = (int)w1;
            } else {
                const unsigned char* p = (const unsigned char*)m;
                g_mask[0] = p[0] ? 1 : 0; g_mask[1] = p[1] ? 1 : 0;
            }
        }
    }
}

// Epilogue store for the fused QKV GEMM (c in [0,1536), even; v0,v1 = c,c+1).
__device__ __forceinline__ void epi_store(int r, int c, float v0, float v1) {
    int seg = c >> 9;
    int off = c & 511;
    size_t p = (size_t)r * 256 + (off >> 1);
    if (seg == 2) {
        g_Vh[p] = packh2(v0, v1);
    } else {
        int pos = r & 31;
        int fi = (c & 63) >> 1;
        float cs = g_cos[pos * 32 + fi];
        float sn = g_sin[pos * 32 + fi];
        if (seg == 0) { v0 *= 0.125f; v1 *= 0.125f; }
        uint32_t w = packh2(v0 * cs - v1 * sn, v1 * cs + v0 * sn);
        ((seg == 0) ? g_Qh : g_Kh)[p] = w;
    }
}

// ---------------- fp16 mma.sync GEMM, 3-stage cp.async, ldmatrix A ----------
// C[M,N] = A[M,512]*B[512,N]; block 128x128, BK=32 (2 k16 steps), 8 warps
// (2x4), warp tile 64x32 of m16n8k16. Operand pointers selected device-side.
// A smem: uint32 pairs A[m][k2], row stride 20 words (LDSM quads 5m+c: CF)
// B smem: uint32 pairs B[k2][n], row stride 136 words (frag banks 8t+g: CF)
#define AS_STRIDE 20
#define BS_STRIDE 136
#define AS_WORDS (128 * AS_STRIDE)   // 2560
#define BS_WORDS (16 * BS_STRIDE)    // 2176
#define STG_WORDS (AS_WORDS + BS_WORDS)
#define GEMM_SMEM_BYTES (3 * STG_WORDS * 4)

template <int FUSED>
__global__ __launch_bounds__(256, 2) void gemm_kernel(float* __restrict__ Cout)
{
    extern __shared__ uint32_t sw[];

    const uint32_t* const Apack = FUSED ? g_Xp : g_AOp;
    const uint32_t* const Bpack = FUSED ? g_WQKVp : g_WOp;

    const int tid = threadIdx.x;
    const int warp = tid >> 5, lane = tid & 31;
    const int wm = (warp >> 2) * 64, wn = (warp & 3) * 32;
    const int grp = lane >> 2, tig = lane & 3;
    const int rowBase = blockIdx.y * 128;
    const int bx = blockIdx.x;
    const int ldBp = FUSED ? 1536 : 512;
    const int nb = bx * 128;
    const uint32_t sbase = smem_u32(sw);

    auto ISSUE = [&](int c, int s) {
        const uint32_t stg = sbase + (uint32_t)s * STG_WORDS * 4;
#pragma unroll
        for (int i = 0; i < 2; i++) {
            int op = tid + 256 * i;
            int row = op >> 2, c4 = (op & 3) * 4;
            cp16(stg + (uint32_t)(row * AS_STRIDE + c4) * 4,
                 Apack + (size_t)(rowBase + row) * 256 + c * 16 + c4);
        }
#pragma unroll
        for (int i = 0; i < 2; i++) {
            int op = tid + 256 * i;
            int r = op >> 5, n4 = (op & 31) * 4;
            cp16(stg + (uint32_t)(AS_WORDS + r * BS_STRIDE + n4) * 4,
                 Bpack + (size_t)(c * 16 + r) * ldBp + nb + n4);
        }
    };

    // ldmatrix A-address: lane -> row wm+mf*16+(lane&15), word k0 + (lane>>4)*4
    const int lrow = lane & 15, lcol = (lane >> 4) << 2;

    uint32_t af[4][4], bf[4][2];
    auto LOADFRAG = [&](int s, int ks) {
        const int k0 = ks * 8;
        const uint32_t aBase = sbase + (uint32_t)(s * STG_WORDS) * 4;
#pragma unroll
        for (int mf = 0; mf < 4; mf++) {
            uint32_t addr = aBase + (uint32_t)((wm + mf * 16 + lrow) * AS_STRIDE + k0 + lcol) * 4;
            asm volatile(
                "ldmatrix.sync.aligned.m8n8.x4.shared.b16 {%0,%1,%2,%3}, [%4];"
                : "=r"(af[mf][0]), "=r"(af[mf][1]), "=r"(af[mf][2]), "=r"(af[mf][3])
                : "r"(addr));
        }
        const uint32_t* bs = sw + s * STG_WORDS + AS_WORDS;
#pragma unroll
        for (int nf = 0; nf < 4; nf++) {
            int nc = wn + nf * 8 + grp;
            bf[nf][0] = bs[(k0 + tig) * BS_STRIDE + nc];
            bf[nf][1] = bs[(k0 + tig + 4) * BS_STRIDE + nc];
        }
    };

    float acc[4][4][4];
#pragma unroll
    for (int a = 0; a < 4; a++)
#pragma unroll
        for (int b = 0; b < 4; b++)
#pragma unroll
            for (int c = 0; c < 4; c++) acc[a][b][c] = 0.0f;

    ISSUE(0, 0); cp_commit();
    ISSUE(1, 1); cp_commit();

#pragma unroll 1
    for (int c = 0; c < 16; c++) {
        const int s = c % 3;
        if (c < 14)
            asm volatile("cp.async.wait_group 1;" ::: "memory");
        else
            asm volatile("cp.async.wait_group 0;" ::: "memory");
        __syncthreads();
        if (c < 14) { ISSUE(c + 2, (c + 2) % 3); cp_commit(); }
#pragma unroll
        for (int ks = 0; ks < 2; ks++) {
            LOADFRAG(s, ks);
#pragma unroll
            for (int mf = 0; mf < 4; mf++)
#pragma unroll
                for (int nf = 0; nf < 4; nf++) {
                    asm volatile(
                        "mma.sync.aligned.m16n8k16.row.col.f32.f16.f16.f32 "
                        "{%0,%1,%2,%3}, {%4,%5,%6,%7}, {%8,%9}, {%0,%1,%2,%3};\n"
                        : "+f"(acc[mf][nf][0]), "+f"(acc[mf][nf][1]),
                          "+f"(acc[mf][nf][2]), "+f"(acc[mf][nf][3])
                        : "r"(af[mf][0]), "r"(af[mf][1]),
                          "r"(af[mf][2]), "r"(af[mf][3]),
                          "r"(bf[nf][0]), "r"(bf[nf][1]));
                }
        }
    }

    // -------- epilogue --------
    const int cBase = bx * 128 + wn;
#pragma unroll
    for (int mf = 0; mf < 4; mf++) {
        int r = rowBase + wm + mf * 16 + grp;
#pragma unroll
        for (int nf = 0; nf < 4; nf++) {
            int c = cBase + nf * 8 + 2 * tig;
            if (FUSED) {
                epi_store(r,     c, acc[mf][nf][0], acc[mf][nf][1]);
                epi_store(r + 8, c, acc[mf][nf][2], acc[mf][nf][3]);
            } else {
                *(float2*)(Cout + (size_t)r * 512 + c) =
                    make_float2(acc[mf][nf][0], acc[mf][nf][1]);
                *(float2*)(Cout + (size_t)(r + 8) * 512 + c) =
                    make_float2(acc[mf][nf][2], acc[mf][nf][3]);
            }
        }
    }
}

// ---------------- attention: one block per (b,s,h) --------------------------
// Reads fp16 Q/K/V, fp32 smem compute, writes packed half2 to g_AOp.
// sim loop float4-vectorized; thread (i, jb) covers j = jb + 8r (CF quads).
__global__ __launch_bounds__(256) void attn_kernel(const float* __restrict__ pos_bias)
{
    const int blk = blockIdx.x;        // 16384 = 2*1024*8
    const int h = blk & 7;
    const int bs = blk >> 3;
    const int b = bs >> 10;
    const int r0 = bs * 32;
    const int tid = threadIdx.x;
    const int hw = h * 32;             // head offset in half2 words

    if (g_mask[b]) {
        // attn = I -> out = v exactly (same fp16 values pass through)
        int row = tid >> 3, w4 = (tid & 7) * 4;
        size_t p = (size_t)(r0 + row) * 256 + hw + w4;
        *(uint4*)&g_AOp[p] = *(const uint4*)&g_Vh[p];
        return;
    }

    __shared__ float sQ[32][68];
    __shared__ float sK[32][68];
    __shared__ float sV[32][72];
    __shared__ float sS[32][33];

    {
        int row = tid >> 3, w4 = (tid & 7) * 4;   // 4 half2 words = 8 floats
        size_t p = (size_t)(r0 + row) * 256 + hw + w4;
        uint4 qw = *(const uint4*)&g_Qh[p];
        uint4 kw = *(const uint4*)&g_Kh[p];
        uint4 vw = *(const uint4*)&g_Vh[p];
        int d = w4 * 2;
        uint32_t qa[4] = {qw.x, qw.y, qw.z, qw.w};
        uint32_t ka[4] = {kw.x, kw.y, kw.z, kw.w};
        uint32_t va[4] = {vw.x, vw.y, vw.z, vw.w};
#pragma unroll
        for (int j = 0; j < 4; j++) {
            float2 q = unpackh2(qa[j]);
            float2 k = unpackh2(ka[j]);
            float2 v = unpackh2(va[j]);
            sQ[row][d + 2 * j]     = q.x; sQ[row][d + 2 * j + 1] = q.y;
            sK[row][d + 2 * j]     = k.x; sK[row][d + 2 * j + 1] = k.y;
            sV[row][d + 2 * j]     = v.x; sV[row][d + 2 * j + 1] = v.y;
        }
    }
    __syncthreads();

    // sim[i][j] = q_i . k_j + pos_bias; thread -> (i = tid>>3, j = (tid&7)+8r)
    const int i = tid >> 3;
    const int jb = tid & 7;
    float s0 = 0.f, s1 = 0.f, s2 = 0.f, s3 = 0.f;
#pragma unroll
    for (int d4 = 0; d4 < 64; d4 += 4) {
        float4 q = *(const float4*)&sQ[i][d4];
        float4 k0 = *(const float4*)&sK[jb][d4];
        float4 k1 = *(const float4*)&sK[jb + 8][d4];
        float4 k2 = *(const float4*)&sK[jb + 16][d4];
        float4 k3 = *(const float4*)&sK[jb + 24][d4];
        s0 += q.x * k0.x + q.y * k0.y + q.z * k0.z + q.w * k0.w;
        s1 += q.x * k1.x + q.y * k1.y + q.z * k1.z + q.w * k1.w;
        s2 += q.x * k2.x + q.y * k2.y + q.z * k2.z + q.w * k2.w;
        s3 += q.x * k3.x + q.y * k3.y + q.z * k3.z + q.w * k3.w;
    }
    const float* pb = pos_bias + (size_t)h * 1024 + i * 32 + jb;
    sS[i][jb +  0] = s0 + pb[0];
    sS[i][jb +  8] = s1 + pb[8];
    sS[i][jb + 16] = s2 + pb[16];
    sS[i][jb + 24] = s3 + pb[24];
    __syncthreads();

    // softmax: warp w -> rows 4w..4w+3, one lane per column
    const int warp = tid >> 5, lane = tid & 31;
#pragma unroll
    for (int rr = 0; rr < 4; rr++) {
        int row = warp * 4 + rr;
        float v = sS[row][lane];
        float m = v;
#pragma unroll
        for (int o = 16; o > 0; o >>= 1) m = fmaxf(m, __shfl_xor_sync(0xffffffffu, m, o));
        float e = expf(v - m);
        float sum = e;
#pragma unroll
        for (int o = 16; o > 0; o >>= 1) sum += __shfl_xor_sync(0xffffffffu, sum, o);
        sS[row][lane] = e / sum;
    }
    __syncthreads();

    // out[i][d] = sum_j attn[i][j] * v[j][d]; thread -> (row i, 8 d's)
    const int db = (tid & 7) * 8;
    float4 o0 = make_float4(0.f, 0.f, 0.f, 0.f);
    float4 o1 = make_float4(0.f, 0.f, 0.f, 0.f);
#pragma unroll
    for (int j = 0; j < 32; j++) {
        float a = sS[i][j];
        float4 v0 = *(const float4*)&sV[j][db];
        float4 v1 = *(const float4*)&sV[j][db + 4];
        o0.x += a * v0.x; o0.y += a * v0.y; o0.z += a * v0.z; o0.w += a * v0.w;
        o1.x += a * v1.x; o1.y += a * v1.y; o1.z += a * v1.z; o1.w += a * v1.w;
    }
    uint4 w = make_uint4(packh2(o0.x, o0.y), packh2(o0.z, o0.w),
                         packh2(o1.x, o1.y), packh2(o1.z, o1.w));
    *(uint4*)&g_AOp[(size_t)(r0 + i) * 256 + hw + (db >> 1)] = w;
}

// ---------------- launch ------------------------------------------------------
// Inputs resolved by element count (robust to metadata ordering); w_q vs w_out
// (both 262144) disambiguated by position relative to w_kv.
extern "C" void kernel_launch(void* const* d_in, const int* in_sizes, int n_in,
                              void* d_out, int out_size)
{
    (void)out_size;
    int ix = -1, ipb = -1, ifoc = -1, ikv = -1, iif = -1;
    int i262[2] = {-1, -1}; int n262 = 0;
    for (int i = 0; i < n_in; i++) {
        switch (in_sizes[i]) {
            case 33554432: ix = i; break;
            case 8192:     ipb = i; break;
            case 2:        ifoc = i; break;
            case 524288:   ikv = i; break;
            case 32:       iif = i; break;
            case 262144:   if (n262 < 2) i262[n262++] = i; break;
            default: break;
        }
    }
    int iq, io;
    if (n262 == 2 && i262[0] < ikv) { iq = i262[0]; io = i262[1]; }
    else                            { io = i262[0]; iq = i262[1]; }

    const float* x        = (const float*)d_in[ix];
    const float* pos_bias = (const float*)d_in[ipb];
    const uint32_t* mask  = (const uint32_t*)d_in[ifoc];
    const float* w_q      = (const float*)d_in[iq];
    const float* w_kv     = (const float*)d_in[ikv];
    const float* w_out    = (const float*)d_in[io];
    const float* inv_freq = (const float*)d_in[iif];
    float* out = (float*)d_out;

    cudaFuncSetAttribute(gemm_kernel<1>, cudaFuncAttributeMaxDynamicSharedMemorySize, GEMM_SMEM_BYTES);
    cudaFuncSetAttribute(gemm_kernel<0>, cudaFuncAttributeMaxDynamicSharedMemorySize, GEMM_SMEM_BYTES);

    setup_kernel<<<16384 + 512 + 1, 256>>>(x, w_q, w_kv, w_out, inv_freq, mask);
    gemm_kernel<1><<<dim3(12, 512), 256, GEMM_SMEM_BYTES>>>(nullptr);
    attn_kernel<<<16384, 256>>>(pos_bias);
    gemm_kernel<0><<<dim3(4, 512), 256, GEMM_SMEM_BYTES>>>(out);
}

// round 8
// speedup vs baseline: 3.5665x; 1.6701x over previous
#include <cuda_runtime.h>
#include <cuda_fp16.h>
#include <cstdint>

// Problem dims (fixed):
//  x: (2,1024,32,512) -> M = 65536 rows of K=512
//  QKV cols = 1536 (Q 0-511, K 512-1023, V 1024-1535), out proj N=512
#define M_TOTAL 65536

// ---------------- scratch (device globals; no runtime allocation) ----------
__device__ uint32_t g_Qh[(size_t)M_TOTAL * 256];    // roped+scaled Q, half2 along d
__device__ uint32_t g_Kh[(size_t)M_TOTAL * 256];    // roped K, half2 along d
__device__ uint32_t g_Vh[(size_t)M_TOTAL * 256];    // V, half2 along d
__device__ uint32_t g_Xp[(size_t)M_TOTAL * 256];    // x as half2 pairs along k
__device__ uint32_t g_AOp[(size_t)M_TOTAL * 256];   // attn out as half2 pairs
__device__ uint32_t g_WQKVp[256 * 1536];            // [k2][n] half2(w[2k2][n], w[2k2+1][n])
__device__ uint32_t g_WOp[256 * 512];
__device__ float    g_cos[1024];
__device__ float    g_sin[1024];
__device__ int      g_mask[2];

// ---------------- helpers ----------------------------------------------------
__device__ __forceinline__ uint32_t packh2(float lo, float hi) {
    __half2 h = __floats2half2_rn(lo, hi);
    return *reinterpret_cast<uint32_t*>(&h);
}
__device__ __forceinline__ float2 unpackh2(uint32_t w) {
    return __half22float2(*reinterpret_cast<__half2*>(&w));
}
__device__ __forceinline__ uint32_t smem_u32(const void* p) {
    uint32_t a;
    asm("{ .reg .u64 t; cvta.to.shared.u64 t, %1; cvt.u32.u64 %0, t; }"
        : "=r"(a) : "l"(p));
    return a;
}
__device__ __forceinline__ void cp16(uint32_t dst, const void* src) {
    asm volatile("cp.async.cg.shared.global [%0], [%1], 16;"
                 :: "r"(dst), "l"(src) : "memory");
}
__device__ __forceinline__ void cp_commit() {
    asm volatile("cp.async.commit_group;" ::: "memory");
}

// ---------------- setup: pack x/weights to fp16, rope table, mask -----------
__global__ void setup_kernel(
    const float* __restrict__ x,
    const float* __restrict__ w_q,
    const float* __restrict__ w_kv,
    const float* __restrict__ w_out,
    const float* __restrict__ inv_freq,
    const uint32_t* __restrict__ m)
{
    const int bid = blockIdx.x;
    if (bid < 16384) {
        size_t base = ((size_t)bid * 256 + threadIdx.x) * 4;
#pragma unroll
        for (int j = 0; j < 4; j++) {
            size_t w = base + j;
            float2 v = *(const float2*)(x + 2 * w);
            g_Xp[w] = packh2(v.x, v.y);
        }
    } else if (bid < 16384 + 512) {
        size_t base = ((size_t)(bid - 16384) * 256 + threadIdx.x) * 4;
#pragma unroll
        for (int j = 0; j < 4; j++) {
            size_t w = base + j;
            if (w < 393216) {
                int k2 = (int)(w / 1536), n = (int)(w % 1536);
                float a, b;
                if (n < 512) {
                    a = w_q[(size_t)(2 * k2) * 512 + n];
                    b = w_q[(size_t)(2 * k2 + 1) * 512 + n];
                } else {
                    int nn = n - 512;
                    a = w_kv[(size_t)(2 * k2) * 1024 + nn];
                    b = w_kv[(size_t)(2 * k2 + 1) * 1024 + nn];
                }
                g_WQKVp[w] = packh2(a, b);
            } else {
                size_t w2 = w - 393216;
                int k2 = (int)(w2 / 512), n = (int)(w2 % 512);
                g_WOp[w2] = packh2(w_out[(size_t)(2 * k2) * 512 + n],
                                   w_out[(size_t)(2 * k2 + 1) * 512 + n]);
            }
        }
    } else {
#pragma unroll
        for (int j = 0; j < 4; j++) {
            int t = threadIdx.x * 4 + j;
            float ang = (float)(t >> 5) * inv_freq[t & 31];
            g_cos[t] = cosf(ang);
            g_sin[t] = sinf(ang);
        }
        if (threadIdx.x == 0) {
            uint32_t w0 = m[0], w1 = m[1];
            if (w0 <= 1u && w1 <= 1u) {
                g_mask[0] = (int)w0; g_mask[1] = (int)w1;
            } else {
                const unsigned char* p = (const unsigned char*)m;
                g_mask[0] = p[0] ? 1 : 0; g_mask[1] = p[1] ? 1 : 0;
            }
        }
    }
}

// Epilogue store for the fused QKV GEMM (c in [0,1536), even; v0,v1 = c,c+1).
__device__ __forceinline__ void epi_store(int r, int c, float v0, float v1) {
    int seg = c >> 9;
    int off = c & 511;
    size_t p = (size_t)r * 256 + (off >> 1);
    if (seg == 2) {
        g_Vh[p] = packh2(v0, v1);
    } else {
        int pos = r & 31;
        int fi = (c & 63) >> 1;
        float cs = g_cos[pos * 32 + fi];
        float sn = g_sin[pos * 32 + fi];
        if (seg == 0) { v0 *= 0.125f; v1 *= 0.125f; }
        uint32_t w = packh2(v0 * cs - v1 * sn, v1 * cs + v0 * sn);
        ((seg == 0) ? g_Qh : g_Kh)[p] = w;
    }
}

// ---------------- fp16 mma.sync GEMM, BK=64, 2-stage cp.async, ldmatrix A ---
// C[M,N] = A[M,512]*B[512,N]; block 128x128, BK=64 (4 k16 steps, 8 chunks),
// 8 warps (2x4), warp tile 64x32 of m16n8k16. 64 MMAs/warp between barriers.
// A smem: uint32 pairs A[m][k2], 32 words/row + pad 4 -> stride 36 (LDSM CF)
// B smem: uint32 pairs B[k2][n], row stride 136 words (frag banks 8t+g: CF)
#define AS_STRIDE 36
#define BS_STRIDE 136
#define AS_WORDS (128 * AS_STRIDE)   // 4608
#define BS_WORDS (32 * BS_STRIDE)    // 4352
#define STG_WORDS (AS_WORDS + BS_WORDS)
#define GEMM_SMEM_BYTES (2 * STG_WORDS * 4)

template <int FUSED>
__global__ __launch_bounds__(256, 2) void gemm_kernel(float* __restrict__ Cout)
{
    extern __shared__ uint32_t sw[];

    const uint32_t* const Apack = FUSED ? g_Xp : g_AOp;
    const uint32_t* const Bpack = FUSED ? g_WQKVp : g_WOp;

    const int tid = threadIdx.x;
    const int warp = tid >> 5, lane = tid & 31;
    const int wm = (warp >> 2) * 64, wn = (warp & 3) * 32;
    const int grp = lane >> 2, tig = lane & 3;
    const int rowBase = blockIdx.y * 128;
    const int bx = blockIdx.x;
    const int ldBp = FUSED ? 1536 : 512;
    const int nb = bx * 128;
    const uint32_t sbase = smem_u32(sw);

    auto ISSUE = [&](int c, int s) {
        const uint32_t stg = sbase + (uint32_t)s * STG_WORDS * 4;
        // A: 1024 cp16 ops (128 rows x 32 words, 4/thread)
#pragma unroll
        for (int i = 0; i < 4; i++) {
            int op = tid + 256 * i;
            int row = op >> 3, c4 = (op & 7) * 4;
            cp16(stg + (uint32_t)(row * AS_STRIDE + c4) * 4,
                 Apack + (size_t)(rowBase + row) * 256 + c * 32 + c4);
        }
        // B: 1024 cp16 ops (32 k2-rows x 128 words, 4/thread)
#pragma unroll
        for (int i = 0; i < 4; i++) {
            int op = tid + 256 * i;
            int r = op >> 5, n4 = (op & 31) * 4;
            cp16(stg + (uint32_t)(AS_WORDS + r * BS_STRIDE + n4) * 4,
                 Bpack + (size_t)(c * 32 + r) * ldBp + nb + n4);
        }
    };

    // ldmatrix A-address: lane -> row wm+mf*16+(lane&15), word k0 + (lane>>4)*4
    const int lrow = lane & 15, lcol = (lane >> 4) << 2;

    uint32_t af[4][4], bf[4][2];
    auto LOADFRAG = [&](int s, int ks) {
        const int k0 = ks * 8;
        const uint32_t aBase = sbase + (uint32_t)(s * STG_WORDS) * 4;
#pragma unroll
        for (int mf = 0; mf < 4; mf++) {
            uint32_t addr = aBase + (uint32_t)((wm + mf * 16 + lrow) * AS_STRIDE + k0 + lcol) * 4;
            asm volatile(
                "ldmatrix.sync.aligned.m8n8.x4.shared.b16 {%0,%1,%2,%3}, [%4];"
                : "=r"(af[mf][0]), "=r"(af[mf][1]), "=r"(af[mf][2]), "=r"(af[mf][3])
                : "r"(addr));
        }
        const uint32_t* bs = sw + s * STG_WORDS + AS_WORDS;
#pragma unroll
        for (int nf = 0; nf < 4; nf++) {
            int nc = wn + nf * 8 + grp;
            bf[nf][0] = bs[(k0 + tig) * BS_STRIDE + nc];
            bf[nf][1] = bs[(k0 + tig + 4) * BS_STRIDE + nc];
        }
    };

    float acc[4][4][4];
#pragma unroll
    for (int a = 0; a < 4; a++)
#pragma unroll
        for (int b = 0; b < 4; b++)
#pragma unroll
            for (int c = 0; c < 4; c++) acc[a][b][c] = 0.0f;

    ISSUE(0, 0); cp_commit();

#pragma unroll 1
    for (int c = 0; c < 8; c++) {
        const int s = c & 1;
        asm volatile("cp.async.wait_group 0;" ::: "memory");
        __syncthreads();   // chunk c ready; all warps done reading stage s^1
        if (c < 7) { ISSUE(c + 1, s ^ 1); cp_commit(); }
#pragma unroll
        for (int ks = 0; ks < 4; ks++) {
            LOADFRAG(s, ks);
#pragma unroll
            for (int mf = 0; mf < 4; mf++)
#pragma unroll
                for (int nf = 0; nf < 4; nf++) {
                    asm volatile(
                        "mma.sync.aligned.m16n8k16.row.col.f32.f16.f16.f32 "
                        "{%0,%1,%2,%3}, {%4,%5,%6,%7}, {%8,%9}, {%0,%1,%2,%3};\n"
                        : "+f"(acc[mf][nf][0]), "+f"(acc[mf][nf][1]),
                          "+f"(acc[mf][nf][2]), "+f"(acc[mf][nf][3])
                        : "r"(af[mf][0]), "r"(af[mf][1]),
                          "r"(af[mf][2]), "r"(af[mf][3]),
                          "r"(bf[nf][0]), "r"(bf[nf][1]));
                }
        }
    }

    // -------- epilogue --------
    const int cBase = bx * 128 + wn;
#pragma unroll
    for (int mf = 0; mf < 4; mf++) {
        int r = rowBase + wm + mf * 16 + grp;
#pragma unroll
        for (int nf = 0; nf < 4; nf++) {
            int c = cBase + nf * 8 + 2 * tig;
            if (FUSED) {
                epi_store(r,     c, acc[mf][nf][0], acc[mf][nf][1]);
                epi_store(r + 8, c, acc[mf][nf][2], acc[mf][nf][3]);
            } else {
                *(float2*)(Cout + (size_t)r * 512 + c) =
                    make_float2(acc[mf][nf][0], acc[mf][nf][1]);
                *(float2*)(Cout + (size_t)(r + 8) * 512 + c) =
                    make_float2(acc[mf][nf][2], acc[mf][nf][3]);
            }
        }
    }
}

// ---------------- attention: one block per (b,s,h) --------------------------
// Reads fp16 Q/K/V, fp32 smem compute, writes packed half2 to g_AOp.
__global__ __launch_bounds__(256) void attn_kernel(const float* __restrict__ pos_bias)
{
    const int blk = blockIdx.x;        // 16384 = 2*1024*8
    const int h = blk & 7;
    const int bs = blk >> 3;
    const int b = bs >> 10;
    const int r0 = bs * 32;
    const int tid = threadIdx.x;
    const int hw = h * 32;             // head offset in half2 words

    if (g_mask[b]) {
        // attn = I -> out = v exactly (same fp16 values pass through)
        int row = tid >> 3, w4 = (tid & 7) * 4;
        size_t p = (size_t)(r0 + row) * 256 + hw + w4;
        *(uint4*)&g_AOp[p] = *(const uint4*)&g_Vh[p];
        return;
    }

    __shared__ float sQ[32][68];
    __shared__ float sK[32][68];
    __shared__ float sV[32][72];
    __shared__ float sS[32][33];

    {
        int row = tid >> 3, w4 = (tid & 7) * 4;   // 4 half2 words = 8 floats
        size_t p = (size_t)(r0 + row) * 256 + hw + w4;
        uint4 qw = *(const uint4*)&g_Qh[p];
        uint4 kw = *(const uint4*)&g_Kh[p];
        uint4 vw = *(const uint4*)&g_Vh[p];
        int d = w4 * 2;
        uint32_t qa[4] = {qw.x, qw.y, qw.z, qw.w};
        uint32_t ka[4] = {kw.x, kw.y, kw.z, kw.w};
        uint32_t va[4] = {vw.x, vw.y, vw.z, vw.w};
#pragma unroll
        for (int j = 0; j < 4; j++) {
            float2 q = unpackh2(qa[j]);
            float2 k = unpackh2(ka[j]);
            float2 v = unpackh2(va[j]);
            sQ[row][d + 2 * j]     = q.x; sQ[row][d + 2 * j + 1] = q.y;
            sK[row][d + 2 * j]     = k.x; sK[row][d + 2 * j + 1] = k.y;
            sV[row][d + 2 * j]     = v.x; sV[row][d + 2 * j + 1] = v.y;
        }
    }
    __syncthreads();

    // sim[i][j] = q_i . k_j + pos_bias; thread -> (i = tid>>3, j = (tid&7)+8r)
    const int i = tid >> 3;
    const int jb = tid & 7;
    float s0 = 0.f, s1 = 0.f, s2 = 0.f, s3 = 0.f;
#pragma unroll
    for (int d4 = 0; d4 < 64; d4 += 4) {
        float4 q = *(const float4*)&sQ[i][d4];
        float4 k0 = *(const float4*)&sK[jb][d4];
        float4 k1 = *(const float4*)&sK[jb + 8][d4];
        float4 k2 = *(const float4*)&sK[jb + 16][d4];
        float4 k3 = *(const float4*)&sK[jb + 24][d4];
        s0 += q.x * k0.x + q.y * k0.y + q.z * k0.z + q.w * k0.w;
        s1 += q.x * k1.x + q.y * k1.y + q.z * k1.z + q.w * k1.w;
        s2 += q.x * k2.x + q.y * k2.y + q.z * k2.z + q.w * k2.w;
        s3 += q.x * k3.x + q.y * k3.y + q.z * k3.z + q.w * k3.w;
    }
    const float* pb = pos_bias + (size_t)h * 1024 + i * 32 + jb;
    sS[i][jb +  0] = s0 + pb[0];
    sS[i][jb +  8] = s1 + pb[8];
    sS[i][jb + 16] = s2 + pb[16];
    sS[i][jb + 24] = s3 + pb[24];
    __syncthreads();

    // softmax: warp w -> rows 4w..4w+3, one lane per column
    const int warp = tid >> 5, lane = tid & 31;
#pragma unroll
    for (int rr = 0; rr < 4; rr++) {
        int row = warp * 4 + rr;
        float v = sS[row][lane];
        float m = v;
#pragma unroll
        for (int o = 16; o > 0; o >>= 1) m = fmaxf(m, __shfl_xor_sync(0xffffffffu, m, o));
        float e = expf(v - m);
        float sum = e;
#pragma unroll
        for (int o = 16; o > 0; o >>= 1) sum += __shfl_xor_sync(0xffffffffu, sum, o);
        sS[row][lane] = e / sum;
    }
    __syncthreads();

    // out[i][d] = sum_j attn[i][j] * v[j][d]; thread -> (row i, 8 d's)
    const int db = (tid & 7) * 8;
    float4 o0 = make_float4(0.f, 0.f, 0.f, 0.f);
    float4 o1 = make_float4(0.f, 0.f, 0.f, 0.f);
#pragma unroll
    for (int j = 0; j < 32; j++) {
        float a = sS[i][j];
        float4 v0 = *(const float4*)&sV[j][db];
        float4 v1 = *(const float4*)&sV[j][db + 4];
        o0.x += a * v0.x; o0.y += a * v0.y; o0.z += a * v0.z; o0.w += a * v0.w;
        o1.x += a * v1.x; o1.y += a * v1.y; o1.z += a * v1.z; o1.w += a * v1.w;
    }
    uint4 w = make_uint4(packh2(o0.x, o0.y), packh2(o0.z, o0.w),
                         packh2(o1.x, o1.y), packh2(o1.z, o1.w));
    *(uint4*)&g_AOp[(size_t)(r0 + i) * 256 + hw + (db >> 1)] = w;
}

// ---------------- launch ------------------------------------------------------
// Inputs resolved by element count (robust to metadata ordering); w_q vs w_out
// (both 262144) disambiguated by position relative to w_kv.
extern "C" void kernel_launch(void* const* d_in, const int* in_sizes, int n_in,
                              void* d_out, int out_size)
{
    (void)out_size;
    int ix = -1, ipb = -1, ifoc = -1, ikv = -1, iif = -1;
    int i262[2] = {-1, -1}; int n262 = 0;
    for (int i = 0; i < n_in; i++) {
        switch (in_sizes[i]) {
            case 33554432: ix = i; break;
            case 8192:     ipb = i; break;
            case 2:        ifoc = i; break;
            case 524288:   ikv = i; break;
            case 32:       iif = i; break;
            case 262144:   if (n262 < 2) i262[n262++] = i; break;
            default: break;
        }
    }
    int iq, io;
    if (n262 == 2 && i262[0] < ikv) { iq = i262[0]; io = i262[1]; }
    else                            { io = i262[0]; iq = i262[1]; }

    const float* x        = (const float*)d_in[ix];
    const float* pos_bias = (const float*)d_in[ipb];
    const uint32_t* mask  = (const uint32_t*)d_in[ifoc];
    const float* w_q      = (const float*)d_in[iq];
    const float* w_kv     = (const float*)d_in[ikv];
    const float* w_out    = (const float*)d_in[io];
    const float* inv_freq = (const float*)d_in[iif];
    float* out = (float*)d_out;

    cudaFuncSetAttribute(gemm_kernel<1>, cudaFuncAttributeMaxDynamicSharedMemorySize, GEMM_SMEM_BYTES);
    cudaFuncSetAttribute(gemm_kernel<0>, cudaFuncAttributeMaxDynamicSharedMemorySize, GEMM_SMEM_BYTES);

    setup_kernel<<<16384 + 512 + 1, 256>>>(x, w_q, w_kv, w_out, inv_freq, mask);
    gemm_kernel<1><<<dim3(12, 512), 256, GEMM_SMEM_BYTES>>>(nullptr);
    attn_kernel<<<16384, 256>>>(pos_bias);
    gemm_kernel<0><<<dim3(4, 512), 256, GEMM_SMEM_BYTES>>>(out);
}